// round 3
// baseline (speedup 1.0000x reference)
#include <cuda_runtime.h>
#include <cuda_bf16.h>
#include <math_constants.h>

// Problem constants (fixed shapes per reference)
#define B_  2
#define S_  2048
#define H_  2048
#define NH_ 16
#define NKV_ 4
#define HD_ 64
#define NREP_ (NH_/NKV_)
#define ROWS_ (B_*S_)          // 4096
#define QCOLS_ (NH_*HD_)       // 1024
#define KCOLS_ (NKV_*HD_)      // 256

// Scratch (static device globals — no allocations allowed)
__device__ float g_q[ROWS_ * QCOLS_];
__device__ float g_k[ROWS_ * KCOLS_];
__device__ float g_v[ROWS_ * KCOLS_];
__device__ float g_ao[ROWS_ * QCOLS_];

// ---------------------------------------------------------------------------
// Generic fp32 GEMM: C[M,N] = A[M,K] @ B[K,N]. 64x64 tile, 256 thr, 4x4/thread.
// M % 64 == 0, N % 64 == 0, K % 16 == 0 (true for all uses here).
// ---------------------------------------------------------------------------
__global__ void gemm64(const float* __restrict__ A, const float* __restrict__ Bm,
                       float* __restrict__ C, int M, int N, int K) {
    __shared__ float As[16][64];   // As[k][row]
    __shared__ float Bs[16][64];   // Bs[k][col]

    const int tid = threadIdx.x;
    const int tx = tid & 15;
    const int ty = tid >> 4;
    const int rowBase = blockIdx.y * 64;
    const int colBase = blockIdx.x * 64;

    float acc[4][4];
#pragma unroll
    for (int i = 0; i < 4; i++)
#pragma unroll
        for (int j = 0; j < 4; j++) acc[i][j] = 0.f;

    for (int k0 = 0; k0 < K; k0 += 16) {
        // Load A tile: 64 rows x 16 k
#pragma unroll
        for (int idx = tid; idx < 64 * 16; idx += 256) {
            int r = idx >> 4, kk = idx & 15;
            As[kk][r] = A[(size_t)(rowBase + r) * K + k0 + kk];
        }
        // Load B tile: 16 k x 64 cols (coalesced)
#pragma unroll
        for (int idx = tid; idx < 16 * 64; idx += 256) {
            int kk = idx >> 6, c = idx & 63;
            Bs[kk][c] = Bm[(size_t)(k0 + kk) * N + colBase + c];
        }
        __syncthreads();

#pragma unroll
        for (int kk = 0; kk < 16; kk++) {
            float4 a4 = *(const float4*)&As[kk][ty * 4];
            float4 b4 = *(const float4*)&Bs[kk][tx * 4];
            float av[4] = {a4.x, a4.y, a4.z, a4.w};
            float bv[4] = {b4.x, b4.y, b4.z, b4.w};
#pragma unroll
            for (int i = 0; i < 4; i++)
#pragma unroll
                for (int j = 0; j < 4; j++) acc[i][j] = fmaf(av[i], bv[j], acc[i][j]);
        }
        __syncthreads();
    }

#pragma unroll
    for (int i = 0; i < 4; i++) {
        float4 o = make_float4(acc[i][0], acc[i][1], acc[i][2], acc[i][3]);
        *(float4*)&C[(size_t)(rowBase + ty * 4 + i) * N + colBase + tx * 4] = o;
    }
}

// ---------------------------------------------------------------------------
// Fused RMSNorm + RoPE. One warp per (row, head). head<NH -> q, else k.
// Thread lane holds the (d, d+32) rotate-half pair.
// ---------------------------------------------------------------------------
__global__ void rmsrope(float* __restrict__ q, float* __restrict__ k,
                        const float* __restrict__ cosb, const float* __restrict__ sinb,
                        const float* __restrict__ qw, const float* __restrict__ kw) {
    const int head = blockIdx.x;           // 0..NH+NKV-1
    const int row  = blockIdx.y;           // 0..ROWS_-1
    const int s    = row & (S_ - 1);       // position in sequence
    const int lane = threadIdx.x;          // 0..31

    float* buf;
    const float* w;
    if (head < NH_) { buf = q + (size_t)row * QCOLS_ + head * HD_; w = qw; }
    else            { buf = k + (size_t)row * KCOLS_ + (head - NH_) * HD_; w = kw; }

    float x1 = buf[lane];
    float x2 = buf[lane + 32];
    float ss = x1 * x1 + x2 * x2;
#pragma unroll
    for (int o = 16; o > 0; o >>= 1) ss += __shfl_xor_sync(0xffffffffu, ss, o);
    float r = rsqrtf(ss * (1.0f / HD_) + 1e-6f);
    float n1 = x1 * r * w[lane];
    float n2 = x2 * r * w[lane + 32];

    const float c1 = cosb[s * HD_ + lane];
    const float c2 = cosb[s * HD_ + lane + 32];
    const float s1 = sinb[s * HD_ + lane];
    const float s2 = sinb[s * HD_ + lane + 32];

    // q*c + rotate_half(q)*s : out[i] = n1*c1 - n2*s1 ; out[i+32] = n2*c2 + n1*s2
    buf[lane]      = n1 * c1 - n2 * s1;
    buf[lane + 32] = n2 * c2 + n1 * s2;
}

// ---------------------------------------------------------------------------
// Flash attention (fp32, online softmax). Grid (S/64, NH, B). 256 threads.
// 64 q rows x 64 kv per tile. Causal: only kt <= qt, diagonal masked.
// ---------------------------------------------------------------------------
#define APAD 65
#define ATTN_SMEM (4 * 64 * APAD * 4)

__global__ void attn(const float* __restrict__ Q, const float* __restrict__ Kp,
                     const float* __restrict__ Vp, float* __restrict__ O) {
    const int qt = blockIdx.x;
    const int h  = blockIdx.y;
    const int b  = blockIdx.z;
    const int hk = h / NREP_;

    extern __shared__ float sm[];
    float* QsT = sm;                 // [d][r] : 64 x 65
    float* KsT = sm + 64 * APAD;     // [d][c]
    float* Vs  = sm + 2 * 64 * APAD; // [k][d]
    float* PsT = sm + 3 * 64 * APAD; // [k][r]

    const int tid = threadIdx.x;
    const int tx = tid & 15;
    const int ty = tid >> 4;

    // Load Q tile (transposed in smem)
#pragma unroll
    for (int idx = tid; idx < 64 * 64; idx += 256) {
        int r = idx >> 6, d = idx & 63;
        QsT[d * APAD + r] = Q[((size_t)(b * S_ + qt * 64 + r)) * QCOLS_ + h * HD_ + d];
    }

    float m4[4], l4[4], acc[4][4];
#pragma unroll
    for (int i = 0; i < 4; i++) {
        m4[i] = -CUDART_INF_F;
        l4[i] = 0.f;
#pragma unroll
        for (int j = 0; j < 4; j++) acc[i][j] = 0.f;
    }

    for (int kt = 0; kt <= qt; kt++) {
        __syncthreads();   // previous tile's smem reads done (also covers Q load)
        // Load K (transposed) and V tiles
#pragma unroll
        for (int idx = tid; idx < 64 * 64; idx += 256) {
            int r = idx >> 6, d = idx & 63;
            size_t gk = ((size_t)(b * S_ + kt * 64 + r)) * KCOLS_ + hk * HD_ + d;
            KsT[d * APAD + r] = Kp[gk];
            Vs[r * APAD + d]  = Vp[gk];
        }
        __syncthreads();

        // S = Q K^T * scale
        float sc[4][4];
#pragma unroll
        for (int i = 0; i < 4; i++)
#pragma unroll
            for (int j = 0; j < 4; j++) sc[i][j] = 0.f;

#pragma unroll 8
        for (int kk = 0; kk < 64; kk++) {
            float qv[4], kv[4];
#pragma unroll
            for (int i = 0; i < 4; i++) qv[i] = QsT[kk * APAD + ty * 4 + i];
#pragma unroll
            for (int j = 0; j < 4; j++) kv[j] = KsT[kk * APAD + tx * 4 + j];
#pragma unroll
            for (int i = 0; i < 4; i++)
#pragma unroll
                for (int j = 0; j < 4; j++) sc[i][j] = fmaf(qv[i], kv[j], sc[i][j]);
        }

        const float scale = 0.125f;  // 1/sqrt(64)
        if (kt == qt) {
            // causal mask within diagonal tile
#pragma unroll
            for (int i = 0; i < 4; i++) {
                int qr = ty * 4 + i;
#pragma unroll
                for (int j = 0; j < 4; j++) {
                    int kc = tx * 4 + j;
                    sc[i][j] = (kc > qr) ? -CUDART_INF_F : sc[i][j] * scale;
                }
            }
        } else {
#pragma unroll
            for (int i = 0; i < 4; i++)
#pragma unroll
                for (int j = 0; j < 4; j++) sc[i][j] *= scale;
        }

        // Online softmax per q row (row group = 16 lanes sharing ty)
#pragma unroll
        for (int i = 0; i < 4; i++) {
            float rm = fmaxf(fmaxf(sc[i][0], sc[i][1]), fmaxf(sc[i][2], sc[i][3]));
#pragma unroll
            for (int o = 8; o > 0; o >>= 1) rm = fmaxf(rm, __shfl_xor_sync(0xffffffffu, rm, o));
            float mnew = fmaxf(m4[i], rm);
            float cp = __expf(m4[i] - mnew);   // 0 when m4 was -inf
            m4[i] = mnew;
            float rs = 0.f;
#pragma unroll
            for (int j = 0; j < 4; j++) {
                sc[i][j] = __expf(sc[i][j] - mnew);
                rs += sc[i][j];
            }
#pragma unroll
            for (int o = 8; o > 0; o >>= 1) rs += __shfl_xor_sync(0xffffffffu, rs, o);
            l4[i] = l4[i] * cp + rs;
#pragma unroll
            for (int j = 0; j < 4; j++) acc[i][j] *= cp;
        }

        // Write P (transposed) to smem
#pragma unroll
        for (int i = 0; i < 4; i++)
#pragma unroll
            for (int j = 0; j < 4; j++)
                PsT[(tx * 4 + j) * APAD + ty * 4 + i] = sc[i][j];
        __syncthreads();

        // acc += P @ V
#pragma unroll 8
        for (int kk = 0; kk < 64; kk++) {
            float pv[4], vv[4];
#pragma unroll
            for (int i = 0; i < 4; i++) pv[i] = PsT[kk * APAD + ty * 4 + i];
#pragma unroll
            for (int j = 0; j < 4; j++) vv[j] = Vs[kk * APAD + tx * 4 + j];
#pragma unroll
            for (int i = 0; i < 4; i++)
#pragma unroll
                for (int j = 0; j < 4; j++) acc[i][j] = fmaf(pv[i], vv[j], acc[i][j]);
        }
    }

    // Epilogue: O[b, q, h, d] = acc / l
#pragma unroll
    for (int i = 0; i < 4; i++) {
        float inv = 1.0f / l4[i];
        size_t base = ((size_t)(b * S_ + qt * 64 + ty * 4 + i)) * QCOLS_ + h * HD_ + tx * 4;
#pragma unroll
        for (int j = 0; j < 4; j++) O[base + j] = acc[i][j] * inv;
    }
}

// ---------------------------------------------------------------------------
extern "C" void kernel_launch(void* const* d_in, const int* in_sizes, int n_in,
                              void* d_out, int out_size) {
    // metadata order: x, cos, sin, wq, wk, wv, wo, q_norm_w, k_norm_w
    const float* x    = (const float*)d_in[0];
    const float* cosb = (const float*)d_in[1];
    const float* sinb = (const float*)d_in[2];
    const float* wq   = (const float*)d_in[3];
    const float* wk   = (const float*)d_in[4];
    const float* wv   = (const float*)d_in[5];
    const float* wo   = (const float*)d_in[6];
    const float* qw   = (const float*)d_in[7];
    const float* kw   = (const float*)d_in[8];
    float* out = (float*)d_out;

    float *qb, *kb, *vb, *ao;
    cudaGetSymbolAddress((void**)&qb, g_q);
    cudaGetSymbolAddress((void**)&kb, g_k);
    cudaGetSymbolAddress((void**)&vb, g_v);
    cudaGetSymbolAddress((void**)&ao, g_ao);

    // QKV projections
    gemm64<<<dim3(QCOLS_ / 64, ROWS_ / 64), 256>>>(x, wq, qb, ROWS_, QCOLS_, H_);
    gemm64<<<dim3(KCOLS_ / 64, ROWS_ / 64), 256>>>(x, wk, kb, ROWS_, KCOLS_, H_);
    gemm64<<<dim3(KCOLS_ / 64, ROWS_ / 64), 256>>>(x, wv, vb, ROWS_, KCOLS_, H_);

    // RMSNorm + RoPE on q and k
    rmsrope<<<dim3(NH_ + NKV_, ROWS_), 32>>>(qb, kb, cosb, sinb, qw, kw);

    // Causal GQA attention
    static int smem_set = 0;
    cudaFuncSetAttribute(attn, cudaFuncAttributeMaxDynamicSharedMemorySize, ATTN_SMEM);
    (void)smem_set;
    attn<<<dim3(S_ / 64, NH_, B_), 256, ATTN_SMEM>>>(qb, kb, vb, ao);

    // Output projection
    gemm64<<<dim3(H_ / 64, ROWS_ / 64), 256>>>(ao, wo, out, ROWS_, H_, QCOLS_);
}

// round 4
// speedup vs baseline: 1.0040x; 1.0040x over previous
#include <cuda_runtime.h>
#include <cuda_bf16.h>
#include <math_constants.h>

// Problem constants (fixed shapes per reference)
#define B_  2
#define S_  2048
#define H_  2048
#define NH_ 16
#define NKV_ 4
#define HD_ 64
#define NREP_ (NH_/NKV_)
#define ROWS_ (B_*S_)          // 4096
#define QCOLS_ (NH_*HD_)       // 1024
#define KCOLS_ (NKV_*HD_)      // 256

// Scratch (static device globals — no allocations allowed)
__device__ float g_q[ROWS_ * QCOLS_];
__device__ float g_k[ROWS_ * KCOLS_];
__device__ float g_v[ROWS_ * KCOLS_];
__device__ float g_ao[ROWS_ * QCOLS_];

// ---------------------------------------------------------------------------
// Generic fp32 GEMM: C[M,N] = A[M,K] @ B[K,N]. 64x64 tile, 256 thr, 4x4/thread.
// M % 64 == 0, N % 64 == 0, K % 16 == 0 (true for all uses here).
// ---------------------------------------------------------------------------
__global__ void gemm64(const float* __restrict__ A, const float* __restrict__ Bm,
                       float* __restrict__ C, int M, int N, int K) {
    __shared__ float As[16][64];   // As[k][row]
    __shared__ float Bs[16][64];   // Bs[k][col]

    const int tid = threadIdx.x;
    const int tx = tid & 15;
    const int ty = tid >> 4;
    const int rowBase = blockIdx.y * 64;
    const int colBase = blockIdx.x * 64;

    float acc[4][4];
#pragma unroll
    for (int i = 0; i < 4; i++)
#pragma unroll
        for (int j = 0; j < 4; j++) acc[i][j] = 0.f;

    for (int k0 = 0; k0 < K; k0 += 16) {
        // Load A tile: 64 rows x 16 k
#pragma unroll
        for (int idx = tid; idx < 64 * 16; idx += 256) {
            int r = idx >> 4, kk = idx & 15;
            As[kk][r] = A[(size_t)(rowBase + r) * K + k0 + kk];
        }
        // Load B tile: 16 k x 64 cols (coalesced)
#pragma unroll
        for (int idx = tid; idx < 16 * 64; idx += 256) {
            int kk = idx >> 6, c = idx & 63;
            Bs[kk][c] = Bm[(size_t)(k0 + kk) * N + colBase + c];
        }
        __syncthreads();

#pragma unroll
        for (int kk = 0; kk < 16; kk++) {
            float4 a4 = *(const float4*)&As[kk][ty * 4];
            float4 b4 = *(const float4*)&Bs[kk][tx * 4];
            float av[4] = {a4.x, a4.y, a4.z, a4.w};
            float bv[4] = {b4.x, b4.y, b4.z, b4.w};
#pragma unroll
            for (int i = 0; i < 4; i++)
#pragma unroll
                for (int j = 0; j < 4; j++) acc[i][j] = fmaf(av[i], bv[j], acc[i][j]);
        }
        __syncthreads();
    }

#pragma unroll
    for (int i = 0; i < 4; i++) {
        float4 o = make_float4(acc[i][0], acc[i][1], acc[i][2], acc[i][3]);
        *(float4*)&C[(size_t)(rowBase + ty * 4 + i) * N + colBase + tx * 4] = o;
    }
}

// ---------------------------------------------------------------------------
// Fused RMSNorm + RoPE. One warp per (row, head). head<NH -> q, else k.
// Thread lane holds the (d, d+32) rotate-half pair.
// ---------------------------------------------------------------------------
__global__ void rmsrope(float* __restrict__ q, float* __restrict__ k,
                        const float* __restrict__ cosb, const float* __restrict__ sinb,
                        const float* __restrict__ qw, const float* __restrict__ kw) {
    const int head = blockIdx.x;           // 0..NH+NKV-1
    const int row  = blockIdx.y;           // 0..ROWS_-1
    const int s    = row & (S_ - 1);       // position in sequence
    const int lane = threadIdx.x;          // 0..31

    float* buf;
    const float* w;
    if (head < NH_) { buf = q + (size_t)row * QCOLS_ + head * HD_; w = qw; }
    else            { buf = k + (size_t)row * KCOLS_ + (head - NH_) * HD_; w = kw; }

    float x1 = buf[lane];
    float x2 = buf[lane + 32];
    float ss = x1 * x1 + x2 * x2;
#pragma unroll
    for (int o = 16; o > 0; o >>= 1) ss += __shfl_xor_sync(0xffffffffu, ss, o);
    float r = rsqrtf(ss * (1.0f / HD_) + 1e-6f);
    float n1 = x1 * r * w[lane];
    float n2 = x2 * r * w[lane + 32];

    const float c1 = cosb[s * HD_ + lane];
    const float c2 = cosb[s * HD_ + lane + 32];
    const float s1 = sinb[s * HD_ + lane];
    const float s2 = sinb[s * HD_ + lane + 32];

    // q*c + rotate_half(q)*s : out[i] = n1*c1 - n2*s1 ; out[i+32] = n2*c2 + n1*s2
    buf[lane]      = n1 * c1 - n2 * s1;
    buf[lane + 32] = n2 * c2 + n1 * s2;
}

// ---------------------------------------------------------------------------
// Flash attention (fp32, online softmax). Grid (S/64, NH, B). 256 threads.
// 64 q rows x 64 kv per tile. Causal: only kt <= qt, diagonal masked.
// ---------------------------------------------------------------------------
#define APAD 65
#define ATTN_SMEM (4 * 64 * APAD * 4)

__global__ void attn(const float* __restrict__ Q, const float* __restrict__ Kp,
                     const float* __restrict__ Vp, float* __restrict__ O) {
    const int qt = blockIdx.x;
    const int h  = blockIdx.y;
    const int b  = blockIdx.z;
    const int hk = h / NREP_;

    extern __shared__ float sm[];
    float* QsT = sm;                 // [d][r] : 64 x 65
    float* KsT = sm + 64 * APAD;     // [d][c]
    float* Vs  = sm + 2 * 64 * APAD; // [k][d]
    float* PsT = sm + 3 * 64 * APAD; // [k][r]

    const int tid = threadIdx.x;
    const int tx = tid & 15;
    const int ty = tid >> 4;

    // Load Q tile (transposed in smem)
#pragma unroll
    for (int idx = tid; idx < 64 * 64; idx += 256) {
        int r = idx >> 6, d = idx & 63;
        QsT[d * APAD + r] = Q[((size_t)(b * S_ + qt * 64 + r)) * QCOLS_ + h * HD_ + d];
    }

    float m4[4], l4[4], acc[4][4];
#pragma unroll
    for (int i = 0; i < 4; i++) {
        m4[i] = -CUDART_INF_F;
        l4[i] = 0.f;
#pragma unroll
        for (int j = 0; j < 4; j++) acc[i][j] = 0.f;
    }

    for (int kt = 0; kt <= qt; kt++) {
        __syncthreads();   // previous tile's smem reads done (also covers Q load)
        // Load K (transposed) and V tiles
#pragma unroll
        for (int idx = tid; idx < 64 * 64; idx += 256) {
            int r = idx >> 6, d = idx & 63;
            size_t gk = ((size_t)(b * S_ + kt * 64 + r)) * KCOLS_ + hk * HD_ + d;
            KsT[d * APAD + r] = Kp[gk];
            Vs[r * APAD + d]  = Vp[gk];
        }
        __syncthreads();

        // S = Q K^T * scale
        float sc[4][4];
#pragma unroll
        for (int i = 0; i < 4; i++)
#pragma unroll
            for (int j = 0; j < 4; j++) sc[i][j] = 0.f;

#pragma unroll 8
        for (int kk = 0; kk < 64; kk++) {
            float qv[4], kv[4];
#pragma unroll
            for (int i = 0; i < 4; i++) qv[i] = QsT[kk * APAD + ty * 4 + i];
#pragma unroll
            for (int j = 0; j < 4; j++) kv[j] = KsT[kk * APAD + tx * 4 + j];
#pragma unroll
            for (int i = 0; i < 4; i++)
#pragma unroll
                for (int j = 0; j < 4; j++) sc[i][j] = fmaf(qv[i], kv[j], sc[i][j]);
        }

        const float scale = 0.125f;  // 1/sqrt(64)
        if (kt == qt) {
            // causal mask within diagonal tile
#pragma unroll
            for (int i = 0; i < 4; i++) {
                int qr = ty * 4 + i;
#pragma unroll
                for (int j = 0; j < 4; j++) {
                    int kc = tx * 4 + j;
                    sc[i][j] = (kc > qr) ? -CUDART_INF_F : sc[i][j] * scale;
                }
            }
        } else {
#pragma unroll
            for (int i = 0; i < 4; i++)
#pragma unroll
                for (int j = 0; j < 4; j++) sc[i][j] *= scale;
        }

        // Online softmax per q row (row group = 16 lanes sharing ty)
#pragma unroll
        for (int i = 0; i < 4; i++) {
            float rm = fmaxf(fmaxf(sc[i][0], sc[i][1]), fmaxf(sc[i][2], sc[i][3]));
#pragma unroll
            for (int o = 8; o > 0; o >>= 1) rm = fmaxf(rm, __shfl_xor_sync(0xffffffffu, rm, o));
            float mnew = fmaxf(m4[i], rm);
            float cp = __expf(m4[i] - mnew);   // 0 when m4 was -inf
            m4[i] = mnew;
            float rs = 0.f;
#pragma unroll
            for (int j = 0; j < 4; j++) {
                sc[i][j] = __expf(sc[i][j] - mnew);
                rs += sc[i][j];
            }
#pragma unroll
            for (int o = 8; o > 0; o >>= 1) rs += __shfl_xor_sync(0xffffffffu, rs, o);
            l4[i] = l4[i] * cp + rs;
#pragma unroll
            for (int j = 0; j < 4; j++) acc[i][j] *= cp;
        }

        // Write P (transposed) to smem
#pragma unroll
        for (int i = 0; i < 4; i++)
#pragma unroll
            for (int j = 0; j < 4; j++)
                PsT[(tx * 4 + j) * APAD + ty * 4 + i] = sc[i][j];
        __syncthreads();

        // acc += P @ V
#pragma unroll 8
        for (int kk = 0; kk < 64; kk++) {
            float pv[4], vv[4];
#pragma unroll
            for (int i = 0; i < 4; i++) pv[i] = PsT[kk * APAD + ty * 4 + i];
#pragma unroll
            for (int j = 0; j < 4; j++) vv[j] = Vs[kk * APAD + tx * 4 + j];
#pragma unroll
            for (int i = 0; i < 4; i++)
#pragma unroll
                for (int j = 0; j < 4; j++) acc[i][j] = fmaf(pv[i], vv[j], acc[i][j]);
        }
    }

    // Epilogue: O[b, q, h, d] = acc / l
#pragma unroll
    for (int i = 0; i < 4; i++) {
        float inv = 1.0f / l4[i];
        size_t base = ((size_t)(b * S_ + qt * 64 + ty * 4 + i)) * QCOLS_ + h * HD_ + tx * 4;
#pragma unroll
        for (int j = 0; j < 4; j++) O[base + j] = acc[i][j] * inv;
    }
}

// ---------------------------------------------------------------------------
extern "C" void kernel_launch(void* const* d_in, const int* in_sizes, int n_in,
                              void* d_out, int out_size) {
    // metadata order: x, cos, sin, wq, wk, wv, wo, q_norm_w, k_norm_w
    const float* x    = (const float*)d_in[0];
    const float* cosb = (const float*)d_in[1];
    const float* sinb = (const float*)d_in[2];
    const float* wq   = (const float*)d_in[3];
    const float* wk   = (const float*)d_in[4];
    const float* wv   = (const float*)d_in[5];
    const float* wo   = (const float*)d_in[6];
    const float* qw   = (const float*)d_in[7];
    const float* kw   = (const float*)d_in[8];
    float* out = (float*)d_out;

    float *qb, *kb, *vb, *ao;
    cudaGetSymbolAddress((void**)&qb, g_q);
    cudaGetSymbolAddress((void**)&kb, g_k);
    cudaGetSymbolAddress((void**)&vb, g_v);
    cudaGetSymbolAddress((void**)&ao, g_ao);

    // QKV projections
    gemm64<<<dim3(QCOLS_ / 64, ROWS_ / 64), 256>>>(x, wq, qb, ROWS_, QCOLS_, H_);
    gemm64<<<dim3(KCOLS_ / 64, ROWS_ / 64), 256>>>(x, wk, kb, ROWS_, KCOLS_, H_);
    gemm64<<<dim3(KCOLS_ / 64, ROWS_ / 64), 256>>>(x, wv, vb, ROWS_, KCOLS_, H_);

    // RMSNorm + RoPE on q and k
    rmsrope<<<dim3(NH_ + NKV_, ROWS_), 32>>>(qb, kb, cosb, sinb, qw, kw);

    // Causal GQA attention
    static int smem_set = 0;
    cudaFuncSetAttribute(attn, cudaFuncAttributeMaxDynamicSharedMemorySize, ATTN_SMEM);
    (void)smem_set;
    attn<<<dim3(S_ / 64, NH_, B_), 256, ATTN_SMEM>>>(qb, kb, vb, ao);

    // Output projection
    gemm64<<<dim3(H_ / 64, ROWS_ / 64), 256>>>(ao, wo, out, ROWS_, H_, QCOLS_);
}

// round 6
// speedup vs baseline: 1.0057x; 1.0017x over previous
#include <cuda_runtime.h>
#include <cuda_bf16.h>
#include <math_constants.h>

// Problem constants (fixed shapes per reference)
#define B_  2
#define S_  2048
#define H_  2048
#define NH_ 16
#define NKV_ 4
#define HD_ 64
#define NREP_ (NH_/NKV_)
#define ROWS_ (B_*S_)          // 4096
#define QCOLS_ (NH_*HD_)       // 1024
#define KCOLS_ (NKV_*HD_)      // 256

// Scratch (static device globals — no allocations allowed)
__device__ float g_q[ROWS_ * QCOLS_];
__device__ float g_k[ROWS_ * KCOLS_];
__device__ float g_v[ROWS_ * KCOLS_];
__device__ float g_ao[ROWS_ * QCOLS_];

// ---------------------------------------------------------------------------
// Generic fp32 GEMM: C[M,N] = A[M,K] @ B[K,N]. 64x64 tile, 256 thr, 4x4/thread.
// M % 64 == 0, N % 64 == 0, K % 16 == 0 (true for all uses here).
// ---------------------------------------------------------------------------
__global__ void gemm64(const float* __restrict__ A, const float* __restrict__ Bm,
                       float* __restrict__ C, int M, int N, int K) {
    __shared__ float As[16][64];   // As[k][row]
    __shared__ float Bs[16][64];   // Bs[k][col]

    const int tid = threadIdx.x;
    const int tx = tid & 15;
    const int ty = tid >> 4;
    const int rowBase = blockIdx.y * 64;
    const int colBase = blockIdx.x * 64;

    float acc[4][4];
#pragma unroll
    for (int i = 0; i < 4; i++)
#pragma unroll
        for (int j = 0; j < 4; j++) acc[i][j] = 0.f;

    for (int k0 = 0; k0 < K; k0 += 16) {
        // Load A tile: 64 rows x 16 k
#pragma unroll
        for (int idx = tid; idx < 64 * 16; idx += 256) {
            int r = idx >> 4, kk = idx & 15;
            As[kk][r] = A[(size_t)(rowBase + r) * K + k0 + kk];
        }
        // Load B tile: 16 k x 64 cols (coalesced)
#pragma unroll
        for (int idx = tid; idx < 16 * 64; idx += 256) {
            int kk = idx >> 6, c = idx & 63;
            Bs[kk][c] = Bm[(size_t)(k0 + kk) * N + colBase + c];
        }
        __syncthreads();

#pragma unroll
        for (int kk = 0; kk < 16; kk++) {
            float4 a4 = *(const float4*)&As[kk][ty * 4];
            float4 b4 = *(const float4*)&Bs[kk][tx * 4];
            float av[4] = {a4.x, a4.y, a4.z, a4.w};
            float bv[4] = {b4.x, b4.y, b4.z, b4.w};
#pragma unroll
            for (int i = 0; i < 4; i++)
#pragma unroll
                for (int j = 0; j < 4; j++) acc[i][j] = fmaf(av[i], bv[j], acc[i][j]);
        }
        __syncthreads();
    }

#pragma unroll
    for (int i = 0; i < 4; i++) {
        float4 o = make_float4(acc[i][0], acc[i][1], acc[i][2], acc[i][3]);
        *(float4*)&C[(size_t)(rowBase + ty * 4 + i) * N + colBase + tx * 4] = o;
    }
}

// ---------------------------------------------------------------------------
// Fused RMSNorm + RoPE. One warp per (row, head). head<NH -> q, else k.
// Thread lane holds the (d, d+32) rotate-half pair.
// ---------------------------------------------------------------------------
__global__ void rmsrope(float* __restrict__ q, float* __restrict__ k,
                        const float* __restrict__ cosb, const float* __restrict__ sinb,
                        const float* __restrict__ qw, const float* __restrict__ kw) {
    const int head = blockIdx.x;           // 0..NH+NKV-1
    const int row  = blockIdx.y;           // 0..ROWS_-1
    const int s    = row & (S_ - 1);       // position in sequence
    const int lane = threadIdx.x;          // 0..31

    float* buf;
    const float* w;
    if (head < NH_) { buf = q + (size_t)row * QCOLS_ + head * HD_; w = qw; }
    else            { buf = k + (size_t)row * KCOLS_ + (head - NH_) * HD_; w = kw; }

    float x1 = buf[lane];
    float x2 = buf[lane + 32];
    float ss = x1 * x1 + x2 * x2;
#pragma unroll
    for (int o = 16; o > 0; o >>= 1) ss += __shfl_xor_sync(0xffffffffu, ss, o);
    float r = rsqrtf(ss * (1.0f / HD_) + 1e-6f);
    float n1 = x1 * r * w[lane];
    float n2 = x2 * r * w[lane + 32];

    const float c1 = cosb[s * HD_ + lane];
    const float c2 = cosb[s * HD_ + lane + 32];
    const float s1 = sinb[s * HD_ + lane];
    const float s2 = sinb[s * HD_ + lane + 32];

    // q*c + rotate_half(q)*s : out[i] = n1*c1 - n2*s1 ; out[i+32] = n2*c2 + n1*s2
    buf[lane]      = n1 * c1 - n2 * s1;
    buf[lane + 32] = n2 * c2 + n1 * s2;
}

// ---------------------------------------------------------------------------
// Flash attention (fp32, online softmax). Grid (S/64, NH, B). 256 threads.
// 64 q rows x 64 kv per tile. Causal: only kt <= qt, diagonal masked.
// ---------------------------------------------------------------------------
#define APAD 65
#define ATTN_SMEM (4 * 64 * APAD * 4)

__global__ void attn(const float* __restrict__ Q, const float* __restrict__ Kp,
                     const float* __restrict__ Vp, float* __restrict__ O) {
    const int qt = blockIdx.x;
    const int h  = blockIdx.y;
    const int b  = blockIdx.z;
    const int hk = h / NREP_;

    extern __shared__ float sm[];
    float* QsT = sm;                 // [d][r] : 64 x 65
    float* KsT = sm + 64 * APAD;     // [d][c]
    float* Vs  = sm + 2 * 64 * APAD; // [k][d]
    float* PsT = sm + 3 * 64 * APAD; // [k][r]

    const int tid = threadIdx.x;
    const int tx = tid & 15;
    const int ty = tid >> 4;

    // Load Q tile (transposed in smem)
#pragma unroll
    for (int idx = tid; idx < 64 * 64; idx += 256) {
        int r = idx >> 6, d = idx & 63;
        QsT[d * APAD + r] = Q[((size_t)(b * S_ + qt * 64 + r)) * QCOLS_ + h * HD_ + d];
    }

    float m4[4], l4[4], acc[4][4];
#pragma unroll
    for (int i = 0; i < 4; i++) {
        m4[i] = -CUDART_INF_F;
        l4[i] = 0.f;
#pragma unroll
        for (int j = 0; j < 4; j++) acc[i][j] = 0.f;
    }

    for (int kt = 0; kt <= qt; kt++) {
        __syncthreads();   // previous tile's smem reads done (also covers Q load)
        // Load K (transposed) and V tiles
#pragma unroll
        for (int idx = tid; idx < 64 * 64; idx += 256) {
            int r = idx >> 6, d = idx & 63;
            size_t gk = ((size_t)(b * S_ + kt * 64 + r)) * KCOLS_ + hk * HD_ + d;
            KsT[d * APAD + r] = Kp[gk];
            Vs[r * APAD + d]  = Vp[gk];
        }
        __syncthreads();

        // S = Q K^T * scale
        float sc[4][4];
#pragma unroll
        for (int i = 0; i < 4; i++)
#pragma unroll
            for (int j = 0; j < 4; j++) sc[i][j] = 0.f;

#pragma unroll 8
        for (int kk = 0; kk < 64; kk++) {
            float qv[4], kv[4];
#pragma unroll
            for (int i = 0; i < 4; i++) qv[i] = QsT[kk * APAD + ty * 4 + i];
#pragma unroll
            for (int j = 0; j < 4; j++) kv[j] = KsT[kk * APAD + tx * 4 + j];
#pragma unroll
            for (int i = 0; i < 4; i++)
#pragma unroll
                for (int j = 0; j < 4; j++) sc[i][j] = fmaf(qv[i], kv[j], sc[i][j]);
        }

        const float scale = 0.125f;  // 1/sqrt(64)
        if (kt == qt) {
            // causal mask within diagonal tile
#pragma unroll
            for (int i = 0; i < 4; i++) {
                int qr = ty * 4 + i;
#pragma unroll
                for (int j = 0; j < 4; j++) {
                    int kc = tx * 4 + j;
                    sc[i][j] = (kc > qr) ? -CUDART_INF_F : sc[i][j] * scale;
                }
            }
        } else {
#pragma unroll
            for (int i = 0; i < 4; i++)
#pragma unroll
                for (int j = 0; j < 4; j++) sc[i][j] *= scale;
        }

        // Online softmax per q row (row group = 16 lanes sharing ty)
#pragma unroll
        for (int i = 0; i < 4; i++) {
            float rm = fmaxf(fmaxf(sc[i][0], sc[i][1]), fmaxf(sc[i][2], sc[i][3]));
#pragma unroll
            for (int o = 8; o > 0; o >>= 1) rm = fmaxf(rm, __shfl_xor_sync(0xffffffffu, rm, o));
            float mnew = fmaxf(m4[i], rm);
            float cp = __expf(m4[i] - mnew);   // 0 when m4 was -inf
            m4[i] = mnew;
            float rs = 0.f;
#pragma unroll
            for (int j = 0; j < 4; j++) {
                sc[i][j] = __expf(sc[i][j] - mnew);
                rs += sc[i][j];
            }
#pragma unroll
            for (int o = 8; o > 0; o >>= 1) rs += __shfl_xor_sync(0xffffffffu, rs, o);
            l4[i] = l4[i] * cp + rs;
#pragma unroll
            for (int j = 0; j < 4; j++) acc[i][j] *= cp;
        }

        // Write P (transposed) to smem
#pragma unroll
        for (int i = 0; i < 4; i++)
#pragma unroll
            for (int j = 0; j < 4; j++)
                PsT[(tx * 4 + j) * APAD + ty * 4 + i] = sc[i][j];
        __syncthreads();

        // acc += P @ V
#pragma unroll 8
        for (int kk = 0; kk < 64; kk++) {
            float pv[4], vv[4];
#pragma unroll
            for (int i = 0; i < 4; i++) pv[i] = PsT[kk * APAD + ty * 4 + i];
#pragma unroll
            for (int j = 0; j < 4; j++) vv[j] = Vs[kk * APAD + tx * 4 + j];
#pragma unroll
            for (int i = 0; i < 4; i++)
#pragma unroll
                for (int j = 0; j < 4; j++) acc[i][j] = fmaf(pv[i], vv[j], acc[i][j]);
        }
    }

    // Epilogue: O[b, q, h, d] = acc / l
#pragma unroll
    for (int i = 0; i < 4; i++) {
        float inv = 1.0f / l4[i];
        size_t base = ((size_t)(b * S_ + qt * 64 + ty * 4 + i)) * QCOLS_ + h * HD_ + tx * 4;
#pragma unroll
        for (int j = 0; j < 4; j++) O[base + j] = acc[i][j] * inv;
    }
}

// ---------------------------------------------------------------------------
extern "C" void kernel_launch(void* const* d_in, const int* in_sizes, int n_in,
                              void* d_out, int out_size) {
    // metadata order: x, cos, sin, wq, wk, wv, wo, q_norm_w, k_norm_w
    const float* x    = (const float*)d_in[0];
    const float* cosb = (const float*)d_in[1];
    const float* sinb = (const float*)d_in[2];
    const float* wq   = (const float*)d_in[3];
    const float* wk   = (const float*)d_in[4];
    const float* wv   = (const float*)d_in[5];
    const float* wo   = (const float*)d_in[6];
    const float* qw   = (const float*)d_in[7];
    const float* kw   = (const float*)d_in[8];
    float* out = (float*)d_out;

    float *qb, *kb, *vb, *ao;
    cudaGetSymbolAddress((void**)&qb, g_q);
    cudaGetSymbolAddress((void**)&kb, g_k);
    cudaGetSymbolAddress((void**)&vb, g_v);
    cudaGetSymbolAddress((void**)&ao, g_ao);

    // QKV projections
    gemm64<<<dim3(QCOLS_ / 64, ROWS_ / 64), 256>>>(x, wq, qb, ROWS_, QCOLS_, H_);
    gemm64<<<dim3(KCOLS_ / 64, ROWS_ / 64), 256>>>(x, wk, kb, ROWS_, KCOLS_, H_);
    gemm64<<<dim3(KCOLS_ / 64, ROWS_ / 64), 256>>>(x, wv, vb, ROWS_, KCOLS_, H_);

    // RMSNorm + RoPE on q and k
    rmsrope<<<dim3(NH_ + NKV_, ROWS_), 32>>>(qb, kb, cosb, sinb, qw, kw);

    // Causal GQA attention
    static int smem_set = 0;
    cudaFuncSetAttribute(attn, cudaFuncAttributeMaxDynamicSharedMemorySize, ATTN_SMEM);
    (void)smem_set;
    attn<<<dim3(S_ / 64, NH_, B_), 256, ATTN_SMEM>>>(qb, kb, vb, ao);

    // Output projection
    gemm64<<<dim3(H_ / 64, ROWS_ / 64), 256>>>(ao, wo, out, ROWS_, H_, QCOLS_);
}